// round 1
// baseline (speedup 1.0000x reference)
#include <cuda_runtime.h>
#include <cuda_bf16.h>
#include <cstdint>
#include <math.h>

#define NF 512
#define NFIELD 30
#define KDIM 40
#define MT 128
#define NT 64
#define XS_PITCH 520
#define MS_PITCH 520

#define SMEM_XS_BYTES (MT * XS_PITCH * 2)                 // 133120
#define SMEM_MS_OFF   (SMEM_XS_BYTES)
#define SMEM_MS_BYTES (NT * MS_PITCH * 2)                 // 66560
#define SMEM_W1_OFF   (SMEM_MS_OFF + SMEM_MS_BYTES)       // 199680
#define SMEM_ACC_OFF  (SMEM_W1_OFF + NF * 4)              // 201728
#define SMEM_TOTAL    (SMEM_ACC_OFF + MT * 4)             // 202240

// Precomputed interaction matrix G = 0.5*C with zero diagonal, bf16.
__device__ __nv_bfloat16 g_G[NF * NF];

// ---------------------------------------------------------------------------
// Kernel 1: G[j][i] = (i==j) ? 0 : 0.5 * dot(v[i, f2f[j], :], v[j, f2f[i], :])
// (C is symmetric, so row/col orientation is irrelevant.)
// ---------------------------------------------------------------------------
__global__ void build_G_kernel(const float* __restrict__ v, const int* __restrict__ f2f) {
    int j = blockIdx.x;
    int i = threadIdx.x;
    int fj = __ldg(&f2f[j]);
    int fi = __ldg(&f2f[i]);
    const float4* a  = reinterpret_cast<const float4*>(v + ((size_t)i * NFIELD + fj) * KDIM);
    const float4* bp = reinterpret_cast<const float4*>(v + ((size_t)j * NFIELD + fi) * KDIM);
    float s = 0.f;
#pragma unroll
    for (int t = 0; t < KDIM / 4; t++) {
        float4 av = a[t], bv = bp[t];
        s = fmaf(av.x, bv.x, s);
        s = fmaf(av.y, bv.y, s);
        s = fmaf(av.z, bv.z, s);
        s = fmaf(av.w, bv.w, s);
    }
    s *= 0.5f;
    if (i == j) s = 0.f;
    g_G[(size_t)j * NF + i] = __float2bfloat16(s);
}

// ---------------------------------------------------------------------------
// mma.sync / ldmatrix helpers
// ---------------------------------------------------------------------------
__device__ __forceinline__ void ldsm4(uint32_t* r, uint32_t addr) {
    asm volatile("ldmatrix.sync.aligned.m8n8.x4.shared.b16 {%0,%1,%2,%3}, [%4];"
                 : "=r"(r[0]), "=r"(r[1]), "=r"(r[2]), "=r"(r[3])
                 : "r"(addr));
}

__device__ __forceinline__ void mma16816(float* c, const uint32_t* a, const uint32_t* b) {
    asm volatile(
        "mma.sync.aligned.m16n8k16.row.col.f32.bf16.bf16.f32 "
        "{%0,%1,%2,%3}, {%4,%5,%6,%7}, {%8,%9}, {%0,%1,%2,%3};"
        : "+f"(c[0]), "+f"(c[1]), "+f"(c[2]), "+f"(c[3])
        : "r"(a[0]), "r"(a[1]), "r"(a[2]), "r"(a[3]), "r"(b[0]), "r"(b[1]));
}

// ---------------------------------------------------------------------------
// Kernel 2: per 128-row tile, compute sigmoid( b + x.(G x + w1) )
//   - X tile converted to bf16 in smem once (rows 128 x 512, pitch 520)
//   - loop over 8 column tiles (NT=64) of G
//   - mma accumulators initialized with w1[j]  -> epilogue x.D gives
//     inter + linear in one pass
// ---------------------------------------------------------------------------
__global__ __launch_bounds__(256, 1)
void ffm_main_kernel(const float* __restrict__ X, const float* __restrict__ w1g,
                     const float* __restrict__ bg, float* __restrict__ out) {
    extern __shared__ char smem[];
    __nv_bfloat16* Xs  = reinterpret_cast<__nv_bfloat16*>(smem);
    __nv_bfloat16* Ms  = reinterpret_cast<__nv_bfloat16*>(smem + SMEM_MS_OFF);
    float*         w1s = reinterpret_cast<float*>(smem + SMEM_W1_OFF);
    float*         accs = reinterpret_cast<float*>(smem + SMEM_ACC_OFF);

    const int tid = threadIdx.x;
    const int rowBase = blockIdx.x * MT;

    if (tid < MT) accs[tid] = 0.f;
    for (int idx = tid; idx < NF; idx += 256) w1s[idx] = w1g[idx];

    // Load + convert X tile (128 x 512 fp32 -> bf16), coalesced float4.
    const float4* Xg = reinterpret_cast<const float4*>(X + (size_t)rowBase * NF);
#pragma unroll 4
    for (int it = 0; it < (MT * NF / 4) / 256; it++) {   // 64 iters
        int idx4 = tid + it * 256;
        int row = idx4 >> 7;     // / (512/4)
        int c4  = idx4 & 127;
        float4 f = Xg[idx4];
        __nv_bfloat162 lo, hi;
        lo.x = __float2bfloat16(f.x); lo.y = __float2bfloat16(f.y);
        hi.x = __float2bfloat16(f.z); hi.y = __float2bfloat16(f.w);
        uint2 u;
        u.x = *reinterpret_cast<uint32_t*>(&lo);
        u.y = *reinterpret_cast<uint32_t*>(&hi);
        *reinterpret_cast<uint2*>(Xs + row * XS_PITCH + c4 * 4) = u;
    }

    const int lane = tid & 31;
    const int wid  = tid >> 5;
    const int warpRow = wid & 3;   // 4 row groups of 32 rows
    const int warpCol = wid >> 2;  // 2 col groups of 32 cols
    const int mBase = warpRow * 32;

    uint32_t xsB = (uint32_t)__cvta_generic_to_shared(Xs);
    uint32_t msB = (uint32_t)__cvta_generic_to_shared(Ms);
    // A (m16k16, x4): row = mBase + msub*16 + lane%16, col half = (lane/16)*8
    uint32_t aAddr0 = xsB + (uint32_t)((((mBase + (lane & 15)) * XS_PITCH) + ((lane >> 4) * 8)) * 2);
    uint32_t aAddr1 = aAddr0 + 16 * XS_PITCH * 2;
    // B (two n8k16 frags per x4): rows are n-index of Ms[n][k]
    int bRow = warpCol * 32 + (lane & 7) + ((lane >> 4) & 1) * 8;
    uint32_t bAddr0 = msB + (uint32_t)(((bRow * MS_PITCH) + (((lane >> 3) & 1) * 8)) * 2);
    uint32_t bAddr1 = bAddr0 + 16 * MS_PITCH * 2;

    const float bias0 = bg[0];

    for (int jt = 0; jt < NF / NT; jt++) {
        const int jBase = jt * NT;
        __syncthreads();   // prior tile's mma reads of Ms complete
        // Load G tile: NT rows (j) x NF cols (k), bf16, uint4 vectorized.
        const uint4* Gg = reinterpret_cast<const uint4*>(g_G + (size_t)jBase * NF);
#pragma unroll
        for (int it = 0; it < (NT * NF / 8) / 256; it++) {   // 16 iters
            int idx = tid + it * 256;
            int r  = idx >> 6;       // / (512/8)
            int c8 = idx & 63;
            uint4 u = Gg[idx];
            *reinterpret_cast<uint4*>(Ms + r * MS_PITCH + c8 * 8) = u;
        }
        __syncthreads();

        // Accumulators, initialized with w1[j] (folds linear term in).
        float acc[2][4][4];
#pragma unroll
        for (int ns = 0; ns < 4; ns++) {
            int j0 = jBase + warpCol * 32 + ns * 8 + (lane & 3) * 2;
            float w0 = w1s[j0], w1v = w1s[j0 + 1];
#pragma unroll
            for (int m = 0; m < 2; m++) {
                acc[m][ns][0] = w0; acc[m][ns][1] = w1v;
                acc[m][ns][2] = w0; acc[m][ns][3] = w1v;
            }
        }

#pragma unroll 4
        for (int k0 = 0; k0 < NF; k0 += 16) {
            uint32_t a0[4], a1[4], b0[4], b1[4];
            ldsm4(a0, aAddr0 + k0 * 2);
            ldsm4(a1, aAddr1 + k0 * 2);
            ldsm4(b0, bAddr0 + k0 * 2);
            ldsm4(b1, bAddr1 + k0 * 2);
            mma16816(acc[0][0], a0, &b0[0]);
            mma16816(acc[0][1], a0, &b0[2]);
            mma16816(acc[0][2], a0, &b1[0]);
            mma16816(acc[0][3], a0, &b1[2]);
            mma16816(acc[1][0], a1, &b0[0]);
            mma16816(acc[1][1], a1, &b0[2]);
            mma16816(acc[1][2], a1, &b1[0]);
            mma16816(acc[1][3], a1, &b1[2]);
        }

        // Epilogue: acc[b] += sum_j D[b,j] * x[b,j]
#pragma unroll
        for (int m = 0; m < 2; m++) {
            int rA = mBase + m * 16 + (lane >> 2);
            int rB = rA + 8;
            float pA = 0.f, pB = 0.f;
#pragma unroll
            for (int ns = 0; ns < 4; ns++) {
                int j0 = jBase + warpCol * 32 + ns * 8 + (lane & 3) * 2;
                float xA0 = __bfloat162float(Xs[rA * XS_PITCH + j0]);
                float xA1 = __bfloat162float(Xs[rA * XS_PITCH + j0 + 1]);
                float xB0 = __bfloat162float(Xs[rB * XS_PITCH + j0]);
                float xB1 = __bfloat162float(Xs[rB * XS_PITCH + j0 + 1]);
                pA = fmaf(acc[m][ns][0], xA0, pA);
                pA = fmaf(acc[m][ns][1], xA1, pA);
                pB = fmaf(acc[m][ns][2], xB0, pB);
                pB = fmaf(acc[m][ns][3], xB1, pB);
            }
            pA += __shfl_xor_sync(0xffffffffu, pA, 1);
            pA += __shfl_xor_sync(0xffffffffu, pA, 2);
            pB += __shfl_xor_sync(0xffffffffu, pB, 1);
            pB += __shfl_xor_sync(0xffffffffu, pB, 2);
            if ((lane & 3) == 0) {
                atomicAdd(&accs[rA], pA);
                atomicAdd(&accs[rB], pB);
            }
        }
    }

    __syncthreads();
    if (tid < MT) {
        float logit = accs[tid] + bias0;
        out[rowBase + tid] = 1.f / (1.f + expf(-logit));
    }
}

// ---------------------------------------------------------------------------
// kernel_launch
//   inputs (metadata order): X [B,512] f32, w1 [512,1] f32, b [1] f32,
//                            v [512,30,40] f32, feature2field [512] i32
//   output: [B] f32
// ---------------------------------------------------------------------------
extern "C" void kernel_launch(void* const* d_in, const int* in_sizes, int n_in,
                              void* d_out, int out_size) {
    const float* X   = (const float*)d_in[0];
    const float* w1  = (const float*)d_in[1];
    const float* b   = (const float*)d_in[2];
    const float* v   = (const float*)d_in[3];
    const int*   f2f = (const int*)d_in[4];
    float* out = (float*)d_out;
    (void)n_in; (void)out_size;

    int Brows = in_sizes[0] / NF;

    cudaFuncSetAttribute(ffm_main_kernel,
                         cudaFuncAttributeMaxDynamicSharedMemorySize, SMEM_TOTAL);

    build_G_kernel<<<NF, NF>>>(v, f2f);
    ffm_main_kernel<<<Brows / MT, 256, SMEM_TOTAL>>>(X, w1, b, out);
}

// round 3
// speedup vs baseline: 1.2286x; 1.2286x over previous
#include <cuda_runtime.h>
#include <cuda_bf16.h>
#include <cstdint>
#include <math.h>

#define NF 512
#define NFIELD 30
#define KDIM 40
#define MT 128          // rows per CTA
#define NT 256          // n per jt sweep (2 sweeps)
#define KC 64           // k per chunk

// ---- smem layout (bytes) ----
#define SM_X      0
#define SM_X_BYTES (MT * NF * 2)            // 131072
#define SM_B      (SM_X + SM_X_BYTES)
#define SM_B_SLOT (NT * KC * 2)             // 32768
#define SM_W1     (SM_B + 2 * SM_B_SLOT)    // 196608
#define SM_ACC    (SM_W1 + NF * 4)          // 198656
#define SM_TOT    (SM_ACC + MT * 4)         // 199168

// Precomputed interaction matrix G = 0.5*C, zero diag, bf16, symmetric.
__device__ __nv_bfloat16 g_G[NF * NF];

// ---------------- helpers ----------------
__device__ __forceinline__ uint32_t smem_u32(const void* p) {
    uint32_t a;
    asm("{ .reg .u64 t; cvta.to.shared.u64 t, %1; cvt.u32.u64 %0, t; }" : "=r"(a) : "l"(p));
    return a;
}
__device__ __forceinline__ uint32_t sw128(uint32_t b) { return b ^ ((b >> 3) & 0x70); }
// X tile: blocked atoms (8 rows x 64 bf16 = 1024B); atom = (r>>3) + (k>>6)*16
__device__ __forceinline__ uint32_t aByte(int r, int k) {
    return (uint32_t)((((r >> 3) + (k >> 6) * 16) << 10) + ((r & 7) << 7) + ((k & 63) << 1));
}
__device__ __forceinline__ void ldsm4(uint32_t* r, uint32_t addr) {
    asm volatile("ldmatrix.sync.aligned.m8n8.x4.shared.b16 {%0,%1,%2,%3}, [%4];"
                 : "=r"(r[0]), "=r"(r[1]), "=r"(r[2]), "=r"(r[3]) : "r"(addr));
}
__device__ __forceinline__ void mma16816(float* c, const uint32_t* a, const uint32_t* b) {
    asm volatile(
        "mma.sync.aligned.m16n8k16.row.col.f32.bf16.bf16.f32 "
        "{%0,%1,%2,%3}, {%4,%5,%6,%7}, {%8,%9}, {%0,%1,%2,%3};"
        : "+f"(c[0]), "+f"(c[1]), "+f"(c[2]), "+f"(c[3])
        : "r"(a[0]), "r"(a[1]), "r"(a[2]), "r"(a[3]), "r"(b[0]), "r"(b[1]));
}
__device__ __forceinline__ void cp16(uint32_t dst, const void* src) {
    asm volatile("cp.async.cg.shared.global [%0], [%1], 16;" :: "r"(dst), "l"(src) : "memory");
}
#define CP_COMMIT() asm volatile("cp.async.commit_group;" ::: "memory")

// ---------------------------------------------------------------------------
// Kernel 1: G symmetric — compute i>=j, write both mirrors.
// ---------------------------------------------------------------------------
__global__ void build_G_kernel(const float* __restrict__ v, const int* __restrict__ f2f) {
    int j = blockIdx.x;
    int i = threadIdx.x;
    if (i < j) return;
    int fj = __ldg(&f2f[j]);
    int fi = __ldg(&f2f[i]);
    const float4* a  = reinterpret_cast<const float4*>(v + ((size_t)i * NFIELD + fj) * KDIM);
    const float4* bp = reinterpret_cast<const float4*>(v + ((size_t)j * NFIELD + fi) * KDIM);
    float s = 0.f;
#pragma unroll
    for (int t = 0; t < KDIM / 4; t++) {
        float4 av = a[t], bv = bp[t];
        s = fmaf(av.x, bv.x, s);
        s = fmaf(av.y, bv.y, s);
        s = fmaf(av.z, bv.z, s);
        s = fmaf(av.w, bv.w, s);
    }
    s *= 0.5f;
    if (i == j) s = 0.f;
    __nv_bfloat16 h = __float2bfloat16(s);
    g_G[(size_t)j * NF + i] = h;
    g_G[(size_t)i * NF + j] = h;
}

// ---------------------------------------------------------------------------
// Kernel 2: HMMA GEMM-quadratic form with register accumulators.
//   Warp grid: wm = wid&1 (2 x 64 rows), wn = wid>>1 (4 x 64 cols of NT=256).
//   Per-warp tile m64 x n64, acc[4][8][4] fp32 regs.
//   k streamed in 16 chunks of 64 (2 n-sweeps x 8 k-chunks), cp.async 2-slot.
// ---------------------------------------------------------------------------
__global__ __launch_bounds__(256, 1)
void ffm_hmma_kernel(const float* __restrict__ X, const float* __restrict__ w1g,
                     const float* __restrict__ bg, float* __restrict__ out) {
    extern __shared__ __align__(1024) char smem[];
    const int tid  = threadIdx.x;
    const int lane = tid & 31;
    const int wid  = tid >> 5;
    const int wm   = wid & 1;
    const int wn   = wid >> 1;

    uint32_t sb = smem_u32(smem);
    float* w1s  = reinterpret_cast<float*>(smem + SM_W1);
    float* accs = reinterpret_cast<float*>(smem + SM_ACC);

    if (tid < MT) accs[tid] = 0.f;
    for (int i = tid; i < NF; i += 256) w1s[i] = w1g[i];

    // ---- X prologue: 128 x 512 f32 -> bf16, swizzled blocked atoms ----
    const float4* Xg = reinterpret_cast<const float4*>(X + (size_t)blockIdx.x * MT * NF);
#pragma unroll 4
    for (int it = 0; it < 64; it++) {
        int f = tid + it * 256;
        int r = f >> 7;             // 128 float4 per row
        int k = (f & 127) * 4;
        float4 x4 = Xg[f];
        __nv_bfloat162 lo, hi;
        lo.x = __float2bfloat16(x4.x); lo.y = __float2bfloat16(x4.y);
        hi.x = __float2bfloat16(x4.z); hi.y = __float2bfloat16(x4.w);
        uint2 u;
        u.x = *reinterpret_cast<uint32_t*>(&lo);
        u.y = *reinterpret_cast<uint32_t*>(&hi);
        *reinterpret_cast<uint2*>(smem + SM_X + sw128(aByte(r, k))) = u;
    }

    // ---- G chunk stager: chunk t -> jt = t>>3 (n-half), kc = t&7 ----
    auto issue = [&](int t) {
        int jt = t >> 3, kc = t & 7;
        uint32_t slot = sb + SM_B + (t & 1) * SM_B_SLOT;
        const __nv_bfloat16* gb = g_G + (size_t)jt * NT * NF + kc * KC;
#pragma unroll
        for (int i = 0; i < 8; i++) {
            int flat = tid + i * 256;
            int n = flat >> 3, kq = flat & 7;
            uint32_t byte = ((uint32_t)(n >> 3) << 10) + ((n & 7) << 7) + (kq << 4);
            cp16(slot + sw128(byte), gb + (size_t)n * NF + kq * 8);
        }
        CP_COMMIT();
    };
    issue(0);

    // ---- per-lane ldsm address constants (swizzle folded: disjoint bits) ----
    uint32_t koffA[4], koffB[4];
#pragma unroll
    for (int ks = 0; ks < 4; ks++) {
        koffA[ks] = ((uint32_t)((lane >> 4) << 4) | (ks << 5)) ^ ((lane & 7) << 4);
        koffB[ks] = ((uint32_t)(((lane >> 3) & 1) << 4) | (ks << 5)) ^ ((lane & 7) << 4);
    }
    uint32_t aRowB[4], bRowB[4];
#pragma unroll
    for (int mf = 0; mf < 4; mf++)
        aRowB[mf] = sb + SM_X +
            (uint32_t)(((wm * 8 + mf * 2 + ((lane >> 3) & 1)) << 10) | ((lane & 7) << 7));
#pragma unroll
    for (int nf = 0; nf < 4; nf++)
        bRowB[nf] = (uint32_t)(((wn * 8 + nf * 2 + ((lane >> 4) & 1)) << 10) | ((lane & 7) << 7));

    float acc[4][8][4];
#pragma unroll
    for (int mf = 0; mf < 4; mf++)
#pragma unroll
        for (int nf = 0; nf < 8; nf++)
#pragma unroll
            for (int q = 0; q < 4; q++) acc[mf][nf][q] = 0.f;

    const float bias0 = bg[0];

#pragma unroll 1
    for (int t = 0; t < 16; t++) {
        if (t < 15) { issue(t + 1); asm volatile("cp.async.wait_group 1;" ::: "memory"); }
        else        {               asm volatile("cp.async.wait_group 0;" ::: "memory"); }
        __syncthreads();   // chunk t visible; (t=0: also X tile visible)

        uint32_t slot = sb + SM_B + (t & 1) * SM_B_SLOT;
        uint32_t aB[4], bB[4];
#pragma unroll
        for (int mf = 0; mf < 4; mf++) aB[mf] = aRowB[mf] + ((uint32_t)(t & 7) << 14);
#pragma unroll
        for (int nf = 0; nf < 4; nf++) bB[nf] = slot + bRowB[nf];

#pragma unroll
        for (int ks = 0; ks < 4; ks++) {
            uint32_t a[4][4], b[4][4];
#pragma unroll
            for (int mf = 0; mf < 4; mf++) ldsm4(a[mf], aB[mf] + koffA[ks]);
#pragma unroll
            for (int nf = 0; nf < 4; nf++) ldsm4(b[nf], bB[nf] + koffB[ks]);
#pragma unroll
            for (int mf = 0; mf < 4; mf++) {
#pragma unroll
                for (int nf = 0; nf < 4; nf++) {
                    mma16816(acc[mf][2 * nf],     a[mf], &b[nf][0]);
                    mma16816(acc[mf][2 * nf + 1], a[mf], &b[nf][2]);
                }
            }
        }

        if ((t & 7) == 7) {
            // ---- epilogue for this n-sweep: sum += (D + w1) . x ----
            int jt = t >> 3;
#pragma unroll
            for (int mf = 0; mf < 4; mf++) {
                int r0 = wm * 64 + mf * 16 + (lane >> 2);
                int r1 = r0 + 8;
                float pA = 0.f, pB = 0.f;
#pragma unroll
                for (int nf8 = 0; nf8 < 8; nf8++) {
                    int c = jt * 256 + wn * 64 + nf8 * 8 + (lane & 3) * 2;
                    uint32_t xa = *reinterpret_cast<uint32_t*>(smem + SM_X + sw128(aByte(r0, c)));
                    uint32_t xb = *reinterpret_cast<uint32_t*>(smem + SM_X + sw128(aByte(r1, c)));
                    float x0 = __uint_as_float(xa << 16);
                    float x1 = __uint_as_float(xa & 0xffff0000u);
                    float y0 = __uint_as_float(xb << 16);
                    float y1 = __uint_as_float(xb & 0xffff0000u);
                    float w0 = w1s[c], w1v = w1s[c + 1];
                    pA = fmaf(acc[mf][nf8][0] + w0,  x0, pA);
                    pA = fmaf(acc[mf][nf8][1] + w1v, x1, pA);
                    pB = fmaf(acc[mf][nf8][2] + w0,  y0, pB);
                    pB = fmaf(acc[mf][nf8][3] + w1v, y1, pB);
                    acc[mf][nf8][0] = 0.f; acc[mf][nf8][1] = 0.f;
                    acc[mf][nf8][2] = 0.f; acc[mf][nf8][3] = 0.f;
                }
                pA += __shfl_xor_sync(0xffffffffu, pA, 1);
                pA += __shfl_xor_sync(0xffffffffu, pA, 2);
                pB += __shfl_xor_sync(0xffffffffu, pB, 1);
                pB += __shfl_xor_sync(0xffffffffu, pB, 2);
                if ((lane & 3) == 0) {
                    atomicAdd(&accs[r0], pA);
                    atomicAdd(&accs[r1], pB);
                }
            }
        }
        __syncthreads();   // all warps done with slot t&1 before chunk t+2 refills it
    }

    if (tid < MT) {
        float logit = accs[tid] + bias0;
        out[blockIdx.x * MT + tid] = 1.f / (1.f + expf(-logit));
    }
}

// ---------------------------------------------------------------------------
// kernel_launch
//   inputs: X [B,512] f32, w1 [512,1] f32, b [1] f32,
//           v [512,30,40] f32, feature2field [512] i32 ; output [B] f32
// ---------------------------------------------------------------------------
extern "C" void kernel_launch(void* const* d_in, const int* in_sizes, int n_in,
                              void* d_out, int out_size) {
    const float* X   = (const float*)d_in[0];
    const float* w1  = (const float*)d_in[1];
    const float* b   = (const float*)d_in[2];
    const float* v   = (const float*)d_in[3];
    const int*   f2f = (const int*)d_in[4];
    float* out = (float*)d_out;
    (void)n_in; (void)out_size;

    int Brows = in_sizes[0] / NF;

    static bool attr_set = false;
    if (!attr_set) {
        cudaFuncSetAttribute(ffm_hmma_kernel,
                             cudaFuncAttributeMaxDynamicSharedMemorySize, SM_TOT);
        attr_set = true;
    }

    build_G_kernel<<<NF, NF>>>(v, f2f);
    ffm_hmma_kernel<<<Brows / MT, 256, SM_TOT>>>(X, w1, b, out);
}

// round 4
// speedup vs baseline: 1.2910x; 1.0508x over previous
#include <cuda_runtime.h>
#include <cuda_bf16.h>
#include <cstdint>
#include <math.h>

#define NF 512
#define NFIELD 30
#define KDIM 40
#define MT 128          // rows per CTA
#define NT 256          // n per sweep (2 sweeps)
#define KC 64           // k per chunk
#define NTHREADS 512

// ---- smem layout (bytes) ----
#define SM_X      0
#define SM_X_BYTES (MT * NF * 2)            // 131072
#define SM_B      (SM_X + SM_X_BYTES)
#define SM_B_SLOT (NT * KC * 2)             // 32768
#define SM_ACC    (SM_B + 3 * SM_B_SLOT)    // 229376
#define SM_TOT    (SM_ACC + MT * 4)         // 229888

// Precomputed interaction matrix G = 0.5*C, zero diag, bf16, symmetric.
__device__ __nv_bfloat16 g_G[NF * NF];

// ---------------- helpers ----------------
__device__ __forceinline__ uint32_t smem_u32(const void* p) {
    uint32_t a;
    asm("{ .reg .u64 t; cvta.to.shared.u64 t, %1; cvt.u32.u64 %0, t; }" : "=r"(a) : "l"(p));
    return a;
}
__device__ __forceinline__ uint32_t sw128(uint32_t b) { return b ^ ((b >> 3) & 0x70); }
// X tile: blocked atoms (8 rows x 64 bf16 = 1024B); atom = (r>>3) + (k>>6)*16
__device__ __forceinline__ uint32_t aByte(int r, int k) {
    return (uint32_t)((((r >> 3) + (k >> 6) * 16) << 10) + ((r & 7) << 7) + ((k & 63) << 1));
}
__device__ __forceinline__ void ldsm4(uint32_t* r, uint32_t addr) {
    asm volatile("ldmatrix.sync.aligned.m8n8.x4.shared.b16 {%0,%1,%2,%3}, [%4];"
                 : "=r"(r[0]), "=r"(r[1]), "=r"(r[2]), "=r"(r[3]) : "r"(addr));
}
__device__ __forceinline__ void mma16816(float* c, const uint32_t* a, const uint32_t* b) {
    asm volatile(
        "mma.sync.aligned.m16n8k16.row.col.f32.bf16.bf16.f32 "
        "{%0,%1,%2,%3}, {%4,%5,%6,%7}, {%8,%9}, {%0,%1,%2,%3};"
        : "+f"(c[0]), "+f"(c[1]), "+f"(c[2]), "+f"(c[3])
        : "r"(a[0]), "r"(a[1]), "r"(a[2]), "r"(a[3]), "r"(b[0]), "r"(b[1]));
}
__device__ __forceinline__ void cp16(uint32_t dst, const void* src) {
    asm volatile("cp.async.cg.shared.global [%0], [%1], 16;" :: "r"(dst), "l"(src) : "memory");
}
#define CP_COMMIT() asm volatile("cp.async.commit_group;" ::: "memory")

// ---------------------------------------------------------------------------
// Kernel 1: G symmetric — compute i>=j, write both mirrors.
// ---------------------------------------------------------------------------
__global__ void build_G_kernel(const float* __restrict__ v, const int* __restrict__ f2f) {
    int j = blockIdx.x;
    int i = threadIdx.x;
    if (i < j) return;
    int fj = __ldg(&f2f[j]);
    int fi = __ldg(&f2f[i]);
    const float4* a  = reinterpret_cast<const float4*>(v + ((size_t)i * NFIELD + fj) * KDIM);
    const float4* bp = reinterpret_cast<const float4*>(v + ((size_t)j * NFIELD + fi) * KDIM);
    float s = 0.f;
#pragma unroll
    for (int t = 0; t < KDIM / 4; t++) {
        float4 av = a[t], bv = bp[t];
        s = fmaf(av.x, bv.x, s);
        s = fmaf(av.y, bv.y, s);
        s = fmaf(av.z, bv.z, s);
        s = fmaf(av.w, bv.w, s);
    }
    s *= 0.5f;
    if (i == j) s = 0.f;
    __nv_bfloat16 h = __float2bfloat16(s);
    g_G[(size_t)j * NF + i] = h;
    g_G[(size_t)i * NF + j] = h;
}

// ---------------------------------------------------------------------------
// Kernel 2: HMMA quadratic form, 16 warps, warp tile m32 x n64.
//   Warp grid: wm = wid&3 (4 x 32 rows), wn = wid>>2 (4 x 64 cols of NT=256).
//   3-slot cp.async ring over k-chunks of 64; one barrier per chunk.
// ---------------------------------------------------------------------------
__global__ __launch_bounds__(NTHREADS, 1)
void ffm_hmma_kernel(const float* __restrict__ X, const float* __restrict__ w1g,
                     const float* __restrict__ bg, float* __restrict__ out) {
    extern __shared__ __align__(1024) char smem[];
    const int tid  = threadIdx.x;
    const int lane = tid & 31;
    const int wid  = tid >> 5;
    const int wm   = wid & 3;
    const int wn   = wid >> 2;

    uint32_t sb = smem_u32(smem);
    float* accs = reinterpret_cast<float*>(smem + SM_ACC);
    if (tid < MT) accs[tid] = 0.f;

    // ---- G chunk stager: chunk t -> jt = t>>3 (n-half), kc = t&7 ----
    auto issue = [&](int t) {
        int jt = t >> 3, kc = t & 7;
        uint32_t slot = sb + SM_B + (t % 3) * SM_B_SLOT;
        const __nv_bfloat16* gb = g_G + (size_t)jt * NT * NF + kc * KC;
#pragma unroll
        for (int i = 0; i < 4; i++) {
            int flat = tid + i * NTHREADS;       // 0..2047
            int n = flat >> 3, kq = flat & 7;
            uint32_t byte = ((uint32_t)(n >> 3) << 10) + ((n & 7) << 7) + (kq << 4);
            cp16(slot + sw128(byte), gb + (size_t)n * NF + kq * 8);
        }
        CP_COMMIT();
    };
    issue(0);
    issue(1);

    // ---- X prologue: 128 x 512 f32 -> bf16, swizzled blocked atoms ----
    const float4* Xg = reinterpret_cast<const float4*>(X + (size_t)blockIdx.x * MT * NF);
#pragma unroll 4
    for (int it = 0; it < 32; it++) {
        int f = tid + it * NTHREADS;
        int r = f >> 7;             // 128 float4 per row
        int k = (f & 127) * 4;
        float4 x4 = Xg[f];
        __nv_bfloat162 lo, hi;
        lo.x = __float2bfloat16(x4.x); lo.y = __float2bfloat16(x4.y);
        hi.x = __float2bfloat16(x4.z); hi.y = __float2bfloat16(x4.w);
        uint2 u;
        u.x = *reinterpret_cast<uint32_t*>(&lo);
        u.y = *reinterpret_cast<uint32_t*>(&hi);
        *reinterpret_cast<uint2*>(smem + SM_X + sw128(aByte(r, k))) = u;
    }

    // ---- per-lane ldsm address constants (swizzle folded: disjoint bits) ----
    uint32_t koffA[4], koffB[4];
#pragma unroll
    for (int ks = 0; ks < 4; ks++) {
        koffA[ks] = ((uint32_t)((lane >> 4) << 4) | (ks << 5)) ^ ((lane & 7) << 4);
        koffB[ks] = ((uint32_t)(((lane >> 3) & 1) << 4) | (ks << 5)) ^ ((lane & 7) << 4);
    }
    uint32_t aRowB[2], bRowB[4];
#pragma unroll
    for (int mf = 0; mf < 2; mf++)
        aRowB[mf] = sb + SM_X +
            (uint32_t)(((wm * 4 + mf * 2 + ((lane >> 3) & 1)) << 10) | ((lane & 7) << 7));
#pragma unroll
    for (int nf = 0; nf < 4; nf++)
        bRowB[nf] = (uint32_t)(((wn * 8 + nf * 2 + ((lane >> 4) & 1)) << 10) | ((lane & 7) << 7));

    float acc[2][8][4];
    const float bias0 = bg[0];

#pragma unroll 1
    for (int t = 0; t < 16; t++) {
        if (t < 15) asm volatile("cp.async.wait_group 1;" ::: "memory");
        else        asm volatile("cp.async.wait_group 0;" ::: "memory");
        __syncthreads();   // chunk t visible to all; all warps done with chunk t-1
        if (t < 14) issue(t + 2);

        if ((t & 7) == 0) {
            // init accumulators with w1 (folds linear term in)
            int jt = t >> 3;
#pragma unroll
            for (int nf8 = 0; nf8 < 8; nf8++) {
                int c = jt * 256 + wn * 64 + nf8 * 8 + (lane & 3) * 2;
                float w0 = __ldg(&w1g[c]), w1v = __ldg(&w1g[c + 1]);
#pragma unroll
                for (int mf = 0; mf < 2; mf++) {
                    acc[mf][nf8][0] = w0;  acc[mf][nf8][1] = w1v;
                    acc[mf][nf8][2] = w0;  acc[mf][nf8][3] = w1v;
                }
            }
        }

        uint32_t slot = sb + SM_B + (uint32_t)(t % 3) * SM_B_SLOT;
        uint32_t aB[2], bB[4];
#pragma unroll
        for (int mf = 0; mf < 2; mf++) aB[mf] = aRowB[mf] + ((uint32_t)(t & 7) << 14);
#pragma unroll
        for (int nf = 0; nf < 4; nf++) bB[nf] = slot + bRowB[nf];

#pragma unroll
        for (int ks = 0; ks < 4; ks++) {
            uint32_t a[2][4], b[4][4];
#pragma unroll
            for (int mf = 0; mf < 2; mf++) ldsm4(a[mf], aB[mf] + koffA[ks]);
#pragma unroll
            for (int nf = 0; nf < 4; nf++) ldsm4(b[nf], bB[nf] + koffB[ks]);
#pragma unroll
            for (int mf = 0; mf < 2; mf++) {
#pragma unroll
                for (int nf = 0; nf < 4; nf++) {
                    mma16816(acc[mf][2 * nf],     a[mf], &b[nf][0]);
                    mma16816(acc[mf][2 * nf + 1], a[mf], &b[nf][2]);
                }
            }
        }

        if ((t & 7) == 7) {
            // ---- epilogue for this n-sweep: sum += acc . x  (w1 already in) ----
            int jt = t >> 3;
#pragma unroll
            for (int mf = 0; mf < 2; mf++) {
                int r0 = wm * 32 + mf * 16 + (lane >> 2);
                int r1 = r0 + 8;
                float pA = 0.f, pB = 0.f;
#pragma unroll
                for (int nf8 = 0; nf8 < 8; nf8++) {
                    int c = jt * 256 + wn * 64 + nf8 * 8 + (lane & 3) * 2;
                    uint32_t xa = *reinterpret_cast<uint32_t*>(smem + SM_X + sw128(aByte(r0, c)));
                    uint32_t xb = *reinterpret_cast<uint32_t*>(smem + SM_X + sw128(aByte(r1, c)));
                    float x0 = __uint_as_float(xa << 16);
                    float x1 = __uint_as_float(xa & 0xffff0000u);
                    float y0 = __uint_as_float(xb << 16);
                    float y1 = __uint_as_float(xb & 0xffff0000u);
                    pA = fmaf(acc[mf][nf8][0], x0, pA);
                    pA = fmaf(acc[mf][nf8][1], x1, pA);
                    pB = fmaf(acc[mf][nf8][2], y0, pB);
                    pB = fmaf(acc[mf][nf8][3], y1, pB);
                }
                pA += __shfl_xor_sync(0xffffffffu, pA, 1);
                pA += __shfl_xor_sync(0xffffffffu, pA, 2);
                pB += __shfl_xor_sync(0xffffffffu, pB, 1);
                pB += __shfl_xor_sync(0xffffffffu, pB, 2);
                if ((lane & 3) == 0) {
                    atomicAdd(&accs[r0], pA);
                    atomicAdd(&accs[r1], pB);
                }
            }
        }
    }

    __syncthreads();
    if (tid < MT) {
        float logit = accs[tid] + bias0;
        out[blockIdx.x * MT + tid] = 1.f / (1.f + expf(-logit));
    }
}

// ---------------------------------------------------------------------------
// kernel_launch
//   inputs: X [B,512] f32, w1 [512,1] f32, b [1] f32,
//           v [512,30,40] f32, feature2field [512] i32 ; output [B] f32
// ---------------------------------------------------------------------------
extern "C" void kernel_launch(void* const* d_in, const int* in_sizes, int n_in,
                              void* d_out, int out_size) {
    const float* X   = (const float*)d_in[0];
    const float* w1  = (const float*)d_in[1];
    const float* b   = (const float*)d_in[2];
    const float* v   = (const float*)d_in[3];
    const int*   f2f = (const int*)d_in[4];
    float* out = (float*)d_out;
    (void)n_in; (void)out_size;

    int Brows = in_sizes[0] / NF;

    static bool attr_set = false;
    if (!attr_set) {
        cudaFuncSetAttribute(ffm_hmma_kernel,
                             cudaFuncAttributeMaxDynamicSharedMemorySize, SM_TOT);
        attr_set = true;
    }

    build_G_kernel<<<NF, NF>>>(v, f2f);
    ffm_hmma_kernel<<<Brows / MT, NTHREADS, SM_TOT>>>(X, w1, b, out);
}